// round 3
// baseline (speedup 1.0000x reference)
#include <cuda_runtime.h>

#define NMAX 50000
#define EMAX 800000

// Scratch (device globals -- no allocation allowed in kernel_launch)
__device__ float g_hA[NMAX * 64];
__device__ float g_hB[NMAX * 64];
__device__ int   g_deg[NMAX];
__device__ int   g_off[NMAX + 1];
__device__ int   g_cur[NMAX];
__device__ int   g_csr[EMAX];
__device__ int   g_bsum[128];

// ---------------- CSR build ----------------

__global__ void k_zero_deg(int n) {
    int i = blockIdx.x * blockDim.x + threadIdx.x;
    if (i < n) g_deg[i] = 0;
}

__global__ void k_count(const int* __restrict__ ei, int e) {
    int i = blockIdx.x * blockDim.x + threadIdx.x;
    if (i < e) atomicAdd(&g_deg[ei[e + i]], 1);   // row 1 of edge_index = dst
}

// per-1024-node block sums of degree
__global__ void k_blocksum(int n) {
    __shared__ int sm[256];
    int t = threadIdx.x, b = blockIdx.x;
    int base = b * 1024 + t * 4;
    int s = 0;
    #pragma unroll
    for (int u = 0; u < 4; u++) { int i = base + u; if (i < n) s += g_deg[i]; }
    sm[t] = s; __syncthreads();
    #pragma unroll
    for (int o = 128; o; o >>= 1) { if (t < o) sm[t] += sm[t + o]; __syncthreads(); }
    if (t == 0) g_bsum[b] = sm[0];
}

// per-node exclusive offsets; every block redundantly reduces the (<=128)
// block sums for its own prefix -- no separate single-block scan kernel.
__global__ void k_offsets(int n, int e) {
    __shared__ int sm[256];
    int t = threadIdx.x, b = blockIdx.x;

    // prefix of block sums: sum g_bsum[0..b)
    int v0 = (t < b) ? g_bsum[t] : 0;   // b <= nbs <= 128, so t<b is in-bounds
    sm[t] = v0; __syncthreads();
    #pragma unroll
    for (int o = 128; o; o >>= 1) { if (t < o) sm[t] += sm[t + o]; __syncthreads(); }
    int bpre = sm[0];
    __syncthreads();

    // per-node scan within this block's 1024 nodes
    int base = b * 1024 + t * 4;
    int vv[4]; int s = 0;
    #pragma unroll
    for (int u = 0; u < 4; u++) { vv[u] = (base + u < n) ? g_deg[base + u] : 0; s += vv[u]; }
    sm[t] = s; __syncthreads();
    #pragma unroll
    for (int o = 1; o < 256; o <<= 1) {
        int val = (t >= o) ? sm[t - o] : 0;
        __syncthreads();
        sm[t] += val;
        __syncthreads();
    }
    int excl = sm[t] - s + bpre;
    #pragma unroll
    for (int u = 0; u < 4; u++) {
        if (base + u < n) { g_off[base + u] = excl; g_cur[base + u] = excl; excl += vv[u]; }
    }
    if (b == 0 && t == 0) g_off[n] = e;
}

__global__ void k_place(const int* __restrict__ ei, int e) {
    int i = blockIdx.x * blockDim.x + threadIdx.x;
    if (i >= e) return;
    int s = ei[i];
    int d = ei[e + i];
    int pos = atomicAdd(&g_cur[d], 1);
    g_csr[pos] = s;
}

// ---------------- fused layer: gather-mean + [mean|h]@[Wl;Wr] + leaky (+head) ----------------

__device__ __forceinline__ unsigned long long pack2(float a) {
    unsigned long long r;
    asm("mov.b64 %0, {%1, %1};" : "=l"(r) : "f"(a));
    return r;
}
__device__ __forceinline__ unsigned long long fma2(unsigned long long a,
                                                   unsigned long long b,
                                                   unsigned long long c) {
    unsigned long long d;
    asm("fma.rn.f32x2 %0, %1, %2, %3;" : "=l"(d) : "l"(a), "l"(b), "l"(c));
    return d;
}

#define ROWS 128             // nodes per block
#define ASTRIDE 132          // padded row stride (floats): banks = 4*row + k
#define SMEM_FLOATS (ROWS * ASTRIDE + 128 * 64 + 64)

__global__ void __launch_bounds__(128) k_layer(
    const float* __restrict__ h,
    const float* __restrict__ Wl, const float* __restrict__ bl,
    const float* __restrict__ Wr,
    float* __restrict__ out,                    // [n,64]; unused when do_head
    const float* __restrict__ Wo, const float* __restrict__ bo,
    float* __restrict__ outv,                   // [n]; used when do_head
    int n, int do_head)
{
    extern __shared__ float smem[];
    float* As   = smem;                         // [128][132]: k<64 mean, k>=64 root h
    float* Bs   = smem + ROWS * ASTRIDE;        // [128][64]
    float* bias = Bs + 128 * 64;                // [64]
    const int tid = threadIdx.x;
    const int row0 = blockIdx.x * ROWS;

    // ---- stage weights ----
    {
        const float4* wl4 = (const float4*)Wl;
        const float4* wr4 = (const float4*)Wr;
        float4* bs4 = (float4*)Bs;
        #pragma unroll
        for (int i = 0; i < 8; i++) {
            bs4[i * 128 + tid]        = wl4[i * 128 + tid];
            bs4[1024 + i * 128 + tid] = wr4[i * 128 + tid];
        }
        if (tid < 16) ((float4*)bias)[tid] = ((const float4*)bl)[tid];
    }

    // ---- stage root h into As[r][64..128) ----
    #pragma unroll
    for (int jj = 0; jj < 16; jj++) {
        int idx = jj * 128 + tid;        // 2048 float4 total
        int r = idx >> 4;
        int q = idx & 15;
        int grow = row0 + r;
        float4 v = make_float4(0.f, 0.f, 0.f, 0.f);
        if (grow < n) v = *(const float4*)(h + (size_t)grow * 64 + q * 4);
        *(float4*)(As + r * ASTRIDE + 64 + q * 4) = v;
    }

    // ---- gather neighbor means into As[r][0..64) (warp per node) ----
    {
        const int w = tid >> 5, lane = tid & 31;
        for (int i = 0; i < 32; i++) {
            int rl = w + 4 * i;
            int grow = row0 + rl;
            float2 a = make_float2(0.f, 0.f), b2 = make_float2(0.f, 0.f);
            int deg = 0;
            if (grow < n) {
                int beg = g_off[grow];
                int end = g_off[grow + 1];
                deg = end - beg;
                int j = beg;
                for (; j + 7 < end; j += 8) {
                    int s0 = __ldg(g_csr + j),     s1 = __ldg(g_csr + j + 1);
                    int s2 = __ldg(g_csr + j + 2), s3 = __ldg(g_csr + j + 3);
                    int s4 = __ldg(g_csr + j + 4), s5 = __ldg(g_csr + j + 5);
                    int s6 = __ldg(g_csr + j + 6), s7 = __ldg(g_csr + j + 7);
                    float2 v0 = *(const float2*)(h + (size_t)s0 * 64 + lane * 2);
                    float2 v1 = *(const float2*)(h + (size_t)s1 * 64 + lane * 2);
                    float2 v2 = *(const float2*)(h + (size_t)s2 * 64 + lane * 2);
                    float2 v3 = *(const float2*)(h + (size_t)s3 * 64 + lane * 2);
                    float2 v4 = *(const float2*)(h + (size_t)s4 * 64 + lane * 2);
                    float2 v5 = *(const float2*)(h + (size_t)s5 * 64 + lane * 2);
                    float2 v6 = *(const float2*)(h + (size_t)s6 * 64 + lane * 2);
                    float2 v7 = *(const float2*)(h + (size_t)s7 * 64 + lane * 2);
                    a.x += v0.x + v2.x + v4.x + v6.x;
                    a.y += v0.y + v2.y + v4.y + v6.y;
                    b2.x += v1.x + v3.x + v5.x + v7.x;
                    b2.y += v1.y + v3.y + v5.y + v7.y;
                }
                for (; j < end; j++) {
                    int s = __ldg(g_csr + j);
                    float2 v = *(const float2*)(h + (size_t)s * 64 + lane * 2);
                    a.x += v.x; a.y += v.y;
                }
            }
            float inv = 1.0f / fmaxf((float)deg, 1.0f);
            float2 r2;
            r2.x = (a.x + b2.x) * inv;
            r2.y = (a.y + b2.y) * inv;
            *(float2*)(As + rl * ASTRIDE + 2 * lane) = r2;
        }
    }
    __syncthreads();

    // ---- GEMM: 8x8 thread tile, rows interleaved stride 16, cols split halves ----
    const int cgrp = tid & 7;    // col groups: [cgrp*4, cgrp*4+4) and [32+cgrp*4, ...)
    const int rgi  = tid >> 3;   // 0..15; rows rgi + 16*i
    unsigned long long acc[8][4];
    #pragma unroll
    for (int i = 0; i < 8; i++)
        #pragma unroll
        for (int p = 0; p < 4; p++) acc[i][p] = 0ull;

    #pragma unroll 1
    for (int kc = 0; kc < 128; kc += 4) {
        float4 a4[8];
        #pragma unroll
        for (int i = 0; i < 8; i++)
            a4[i] = *(const float4*)(As + (rgi + 16 * i) * ASTRIDE + kc);
        #pragma unroll
        for (int kk = 0; kk < 4; kk++) {
            ulonglong2 bb0 = *(const ulonglong2*)(Bs + (kc + kk) * 64 + cgrp * 4);
            ulonglong2 bb1 = *(const ulonglong2*)(Bs + (kc + kk) * 64 + 32 + cgrp * 4);
            #pragma unroll
            for (int i = 0; i < 8; i++) {
                float av = ((const float*)&a4[i])[kk];
                unsigned long long aa = pack2(av);
                acc[i][0] = fma2(aa, bb0.x, acc[i][0]);
                acc[i][1] = fma2(aa, bb0.y, acc[i][1]);
                acc[i][2] = fma2(aa, bb1.x, acc[i][2]);
                acc[i][3] = fma2(aa, bb1.y, acc[i][3]);
            }
        }
    }

    // ---- epilogue ----
    float4 bias0 = *(const float4*)(bias + cgrp * 4);
    float4 bias1 = *(const float4*)(bias + 32 + cgrp * 4);
    float4 wo0 = make_float4(0.f, 0.f, 0.f, 0.f), wo1 = wo0;
    float bov = 0.f;
    if (do_head) {
        wo0 = *(const float4*)(Wo + cgrp * 4);
        wo1 = *(const float4*)(Wo + 32 + cgrp * 4);
        bov = bo[0];
    }

    #pragma unroll
    for (int i = 0; i < 8; i++) {
        int grow = row0 + rgi + 16 * i;
        float4 o0, o1;
        asm("mov.b64 {%0, %1}, %2;" : "=f"(o0.x), "=f"(o0.y) : "l"(acc[i][0]));
        asm("mov.b64 {%0, %1}, %2;" : "=f"(o0.z), "=f"(o0.w) : "l"(acc[i][1]));
        asm("mov.b64 {%0, %1}, %2;" : "=f"(o1.x), "=f"(o1.y) : "l"(acc[i][2]));
        asm("mov.b64 {%0, %1}, %2;" : "=f"(o1.z), "=f"(o1.w) : "l"(acc[i][3]));
        o0.x += bias0.x; o0.y += bias0.y; o0.z += bias0.z; o0.w += bias0.w;
        o1.x += bias1.x; o1.y += bias1.y; o1.z += bias1.z; o1.w += bias1.w;
        o0.x = o0.x > 0.f ? o0.x : 0.01f * o0.x;
        o0.y = o0.y > 0.f ? o0.y : 0.01f * o0.y;
        o0.z = o0.z > 0.f ? o0.z : 0.01f * o0.z;
        o0.w = o0.w > 0.f ? o0.w : 0.01f * o0.w;
        o1.x = o1.x > 0.f ? o1.x : 0.01f * o1.x;
        o1.y = o1.y > 0.f ? o1.y : 0.01f * o1.y;
        o1.z = o1.z > 0.f ? o1.z : 0.01f * o1.z;
        o1.w = o1.w > 0.f ? o1.w : 0.01f * o1.w;
        if (do_head) {
            float p = o0.x * wo0.x + o0.y * wo0.y + o0.z * wo0.z + o0.w * wo0.w
                    + o1.x * wo1.x + o1.y * wo1.y + o1.z * wo1.z + o1.w * wo1.w;
            p += __shfl_xor_sync(0xffffffffu, p, 1);
            p += __shfl_xor_sync(0xffffffffu, p, 2);
            p += __shfl_xor_sync(0xffffffffu, p, 4);
            if (cgrp == 0 && grow < n) outv[grow] = p + bov;
        } else if (grow < n) {
            *(float4*)(out + (size_t)grow * 64 + cgrp * 4)      = o0;
            *(float4*)(out + (size_t)grow * 64 + 32 + cgrp * 4) = o1;
        }
    }
}

extern "C" void kernel_launch(void* const* d_in, const int* in_sizes, int n_in,
                              void* d_out, int out_size)
{
    const float* x   = (const float*)d_in[0];
    const int*   ei  = (const int*)d_in[1];
    const float* Wl1 = (const float*)d_in[2];
    const float* bl1 = (const float*)d_in[3];
    const float* Wr1 = (const float*)d_in[4];
    const float* Wl2 = (const float*)d_in[5];
    const float* bl2 = (const float*)d_in[6];
    const float* Wr2 = (const float*)d_in[7];
    const float* Wl3 = (const float*)d_in[8];
    const float* bl3 = (const float*)d_in[9];
    const float* Wr3 = (const float*)d_in[10];
    const float* Wo  = (const float*)d_in[11];
    const float* bo  = (const float*)d_in[12];
    float* out = (float*)d_out;

    const int n = in_sizes[0] / 64;
    const int e = in_sizes[1] / 2;

    float *hA = nullptr, *hB = nullptr;
    cudaGetSymbolAddress((void**)&hA, g_hA);
    cudaGetSymbolAddress((void**)&hB, g_hB);

    const int smem_bytes = SMEM_FLOATS * 4;
    static bool attr_done = false;
    if (!attr_done) {
        cudaFuncSetAttribute(k_layer, cudaFuncAttributeMaxDynamicSharedMemorySize,
                             smem_bytes);
        attr_done = true;
    }

    const int nb  = (n + 255) / 256;
    const int eb  = (e + 255) / 256;
    const int nbs = (n + 1023) / 1024;
    const int lb  = (n + ROWS - 1) / ROWS;

    // CSR build (grouped by destination)
    k_zero_deg<<<nb, 256>>>(n);
    k_count<<<eb, 256>>>(ei, e);
    k_blocksum<<<nbs, 256>>>(n);
    k_offsets<<<nbs, 256>>>(n, e);
    k_place<<<eb, 256>>>(ei, e);

    // fused layers
    k_layer<<<lb, 128, smem_bytes>>>(x,  Wl1, bl1, Wr1, hA, nullptr, nullptr, nullptr, n, 0);
    k_layer<<<lb, 128, smem_bytes>>>(hA, Wl2, bl2, Wr2, hB, nullptr, nullptr, nullptr, n, 0);
    k_layer<<<lb, 128, smem_bytes>>>(hB, Wl3, bl3, Wr3, nullptr, Wo, bo, out, n, 1);
}

// round 4
// speedup vs baseline: 1.7483x; 1.7483x over previous
#include <cuda_runtime.h>

#define NMAX 50000
#define EMAX 800000

// Scratch (device globals -- no allocation allowed in kernel_launch)
__device__ float g_agg[NMAX * 64];
__device__ float g_hA[NMAX * 64];
__device__ float g_hB[NMAX * 64];
__device__ int   g_deg[NMAX];
__device__ int   g_off[NMAX + 1];
__device__ int   g_cur[NMAX];
__device__ int   g_csr[EMAX];
__device__ int   g_bsum[128];

// ---------------- CSR build ----------------

__global__ void k_zero_deg(int n) {
    int i = blockIdx.x * blockDim.x + threadIdx.x;
    if (i < n) g_deg[i] = 0;
}

__global__ void k_count(const int* __restrict__ ei, int e) {
    int i = blockIdx.x * blockDim.x + threadIdx.x;
    if (i < e) atomicAdd(&g_deg[ei[e + i]], 1);   // row 1 of edge_index = dst
}

// per-1024-node block sums of degree
__global__ void k_blocksum(int n) {
    __shared__ int sm[256];
    int t = threadIdx.x, b = blockIdx.x;
    int base = b * 1024 + t * 4;
    int s = 0;
    #pragma unroll
    for (int u = 0; u < 4; u++) { int i = base + u; if (i < n) s += g_deg[i]; }
    sm[t] = s; __syncthreads();
    #pragma unroll
    for (int o = 128; o; o >>= 1) { if (t < o) sm[t] += sm[t + o]; __syncthreads(); }
    if (t == 0) g_bsum[b] = sm[0];
}

// per-node exclusive offsets; every block redundantly reduces the (<=128)
// block sums for its own prefix.
__global__ void k_offsets(int n, int e) {
    __shared__ int sm[256];
    int t = threadIdx.x, b = blockIdx.x;

    int v0 = (t < b) ? g_bsum[t] : 0;
    sm[t] = v0; __syncthreads();
    #pragma unroll
    for (int o = 128; o; o >>= 1) { if (t < o) sm[t] += sm[t + o]; __syncthreads(); }
    int bpre = sm[0];
    __syncthreads();

    int base = b * 1024 + t * 4;
    int vv[4]; int s = 0;
    #pragma unroll
    for (int u = 0; u < 4; u++) { vv[u] = (base + u < n) ? g_deg[base + u] : 0; s += vv[u]; }
    sm[t] = s; __syncthreads();
    #pragma unroll
    for (int o = 1; o < 256; o <<= 1) {
        int val = (t >= o) ? sm[t - o] : 0;
        __syncthreads();
        sm[t] += val;
        __syncthreads();
    }
    int excl = sm[t] - s + bpre;
    #pragma unroll
    for (int u = 0; u < 4; u++) {
        if (base + u < n) { g_off[base + u] = excl; g_cur[base + u] = excl; excl += vv[u]; }
    }
    if (b == 0 && t == 0) g_off[n] = e;
}

__global__ void k_place(const int* __restrict__ ei, int e) {
    int i = blockIdx.x * blockDim.x + threadIdx.x;
    if (i >= e) return;
    int s = ei[i];
    int d = ei[e + i];
    int pos = atomicAdd(&g_cur[d], 1);
    g_csr[pos] = s;
}

// ---------------- mean aggregation (half-warp per node, float4 gather) ----------------

__global__ void k_aggregate(const float* __restrict__ h, int n) {
    int hw   = (blockIdx.x * blockDim.x + threadIdx.x) >> 4;   // half-warp id = node
    int lane = threadIdx.x & 15;
    if (hw >= n) return;
    int beg = g_off[hw];
    int end = g_off[hw + 1];

    float4 a = make_float4(0.f, 0.f, 0.f, 0.f);
    float4 b = a, c = a, d = a;
    int j = beg;
    for (; j + 3 < end; j += 4) {
        int s0 = __ldg(g_csr + j),     s1 = __ldg(g_csr + j + 1);
        int s2 = __ldg(g_csr + j + 2), s3 = __ldg(g_csr + j + 3);
        float4 v0 = *(const float4*)(h + (size_t)s0 * 64 + lane * 4);
        float4 v1 = *(const float4*)(h + (size_t)s1 * 64 + lane * 4);
        float4 v2 = *(const float4*)(h + (size_t)s2 * 64 + lane * 4);
        float4 v3 = *(const float4*)(h + (size_t)s3 * 64 + lane * 4);
        a.x += v0.x; a.y += v0.y; a.z += v0.z; a.w += v0.w;
        b.x += v1.x; b.y += v1.y; b.z += v1.z; b.w += v1.w;
        c.x += v2.x; c.y += v2.y; c.z += v2.z; c.w += v2.w;
        d.x += v3.x; d.y += v3.y; d.z += v3.z; d.w += v3.w;
    }
    for (; j < end; j++) {
        int s = __ldg(g_csr + j);
        float4 v = *(const float4*)(h + (size_t)s * 64 + lane * 4);
        a.x += v.x; a.y += v.y; a.z += v.z; a.w += v.w;
    }
    float inv = 1.0f / fmaxf((float)(end - beg), 1.0f);
    float4 r;
    r.x = (a.x + b.x + c.x + d.x) * inv;
    r.y = (a.y + b.y + c.y + d.y) * inv;
    r.z = (a.z + b.z + c.z + d.z) * inv;
    r.w = (a.w + b.w + c.w + d.w) * inv;
    *(float4*)(g_agg + (size_t)hw * 64 + lane * 4) = r;
}

// ---------------- SAGE transform: persistent weights, grid-stride tiles ----------------
// out = leaky( [mean_nb | h] @ [Wl; Wr] + bl )
// 64 threads; tile = 32 rows x 64 cols; thread tile = 8 rows (stride 4) x 4 cols.

__device__ __forceinline__ unsigned long long pack2(float a) {
    unsigned long long r;
    asm("mov.b64 %0, {%1, %1};" : "=l"(r) : "f"(a));
    return r;
}
__device__ __forceinline__ unsigned long long fma2(unsigned long long a,
                                                   unsigned long long b,
                                                   unsigned long long c) {
    unsigned long long d;
    asm("fma.rn.f32x2 %0, %1, %2, %3;" : "=l"(d) : "l"(a), "l"(b), "l"(c));
    return d;
}

#define ASTRIDE 132
#define SMEM_FLOATS (128 * 64 + 32 * ASTRIDE + 64)

__global__ void __launch_bounds__(64) k_transform(
    const float* __restrict__ h,
    const float* __restrict__ Wl, const float* __restrict__ bl,
    const float* __restrict__ Wr,
    float* __restrict__ out, int n, int ntiles)
{
    extern __shared__ float smem[];
    float* Bs   = smem;                 // [128][64]: k<64 -> Wl, k>=64 -> Wr
    float* As   = smem + 128 * 64;      // [32][132]: k<64 mean_nb, k>=64 root h
    float* bias = As + 32 * ASTRIDE;    // [64]
    const int tid = threadIdx.x;

    // stage weights once per block
    {
        const float4* wl4 = (const float4*)Wl;
        const float4* wr4 = (const float4*)Wr;
        float4* bs4 = (float4*)Bs;
        #pragma unroll
        for (int i = 0; i < 16; i++) {
            bs4[i * 64 + tid]        = wl4[i * 64 + tid];
            bs4[1024 + i * 64 + tid] = wr4[i * 64 + tid];
        }
        if (tid < 16) ((float4*)bias)[tid] = ((const float4*)bl)[tid];
    }

    const int rg = tid >> 4;   // 0..3; rows rg + 4*i, i<8
    const int cg = tid & 15;   // cols cg*4..cg*4+3

    for (int tile = blockIdx.x; tile < ntiles; tile += gridDim.x) {
        const int row0 = tile * 32;
        if (tile != blockIdx.x) __syncthreads();   // As reuse guard

        // stage A tile: 1024 float4, 16 per thread
        {
            #pragma unroll
            for (int ii = 0; ii < 16; ii++) {
                int i = ii * 64 + tid;
                int r = i >> 5;             // 32 float4 per logical row
                int q = i & 31;
                int gr = row0 + r;
                float4 v = make_float4(0.f, 0.f, 0.f, 0.f);
                if (gr < n) {
                    if (q < 16) v = *(const float4*)(g_agg + (size_t)gr * 64 + q * 4);
                    else        v = *(const float4*)(h + (size_t)gr * 64 + (q - 16) * 4);
                }
                *(float4*)(As + r * ASTRIDE + q * 4) = v;
            }
        }
        __syncthreads();

        unsigned long long acc0[8], acc1[8];
        #pragma unroll
        for (int i = 0; i < 8; i++) { acc0[i] = 0ull; acc1[i] = 0ull; }

        #pragma unroll 1
        for (int kc = 0; kc < 128; kc += 4) {
            float4 a4[8];
            #pragma unroll
            for (int i = 0; i < 8; i++)
                a4[i] = *(const float4*)(As + (rg + 4 * i) * ASTRIDE + kc);
            #pragma unroll
            for (int kk = 0; kk < 4; kk++) {
                ulonglong2 bb = *(const ulonglong2*)(Bs + (kc + kk) * 64 + cg * 4);
                #pragma unroll
                for (int i = 0; i < 8; i++) {
                    float av = ((const float*)&a4[i])[kk];
                    unsigned long long aa = pack2(av);
                    acc0[i] = fma2(aa, bb.x, acc0[i]);
                    acc1[i] = fma2(aa, bb.y, acc1[i]);
                }
            }
        }

        float4 bv = *(const float4*)(bias + cg * 4);
        #pragma unroll
        for (int i = 0; i < 8; i++) {
            int gr = row0 + rg + 4 * i;
            if (gr < n) {
                float4 o;
                asm("mov.b64 {%0, %1}, %2;" : "=f"(o.x), "=f"(o.y) : "l"(acc0[i]));
                asm("mov.b64 {%0, %1}, %2;" : "=f"(o.z), "=f"(o.w) : "l"(acc1[i]));
                o.x += bv.x; o.y += bv.y; o.z += bv.z; o.w += bv.w;
                o.x = o.x > 0.f ? o.x : 0.01f * o.x;
                o.y = o.y > 0.f ? o.y : 0.01f * o.y;
                o.z = o.z > 0.f ? o.z : 0.01f * o.z;
                o.w = o.w > 0.f ? o.w : 0.01f * o.w;
                *(float4*)(out + (size_t)gr * 64 + cg * 4) = o;
            }
        }
    }
}

// ---------------- output head ----------------

__global__ void k_out(const float* __restrict__ h, const float* __restrict__ Wo,
                      const float* __restrict__ bo, float* __restrict__ out, int n)
{
    int gtid = blockIdx.x * blockDim.x + threadIdx.x;
    int row  = gtid >> 5;
    int lane = gtid & 31;
    if (row >= n) return;
    float2 hv = *(const float2*)(h + (size_t)row * 64 + lane * 2);
    float2 wv = *(const float2*)(Wo + lane * 2);
    float s = hv.x * wv.x + hv.y * wv.y;
    #pragma unroll
    for (int o = 16; o; o >>= 1) s += __shfl_xor_sync(0xffffffffu, s, o);
    if (lane == 0) out[row] = s + bo[0];
}

extern "C" void kernel_launch(void* const* d_in, const int* in_sizes, int n_in,
                              void* d_out, int out_size)
{
    const float* x   = (const float*)d_in[0];
    const int*   ei  = (const int*)d_in[1];
    const float* Wl1 = (const float*)d_in[2];
    const float* bl1 = (const float*)d_in[3];
    const float* Wr1 = (const float*)d_in[4];
    const float* Wl2 = (const float*)d_in[5];
    const float* bl2 = (const float*)d_in[6];
    const float* Wr2 = (const float*)d_in[7];
    const float* Wl3 = (const float*)d_in[8];
    const float* bl3 = (const float*)d_in[9];
    const float* Wr3 = (const float*)d_in[10];
    const float* Wo  = (const float*)d_in[11];
    const float* bo  = (const float*)d_in[12];
    float* out = (float*)d_out;

    const int n = in_sizes[0] / 64;
    const int e = in_sizes[1] / 2;

    float *hA = nullptr, *hB = nullptr;
    cudaGetSymbolAddress((void**)&hA, g_hA);
    cudaGetSymbolAddress((void**)&hB, g_hB);

    const int smem_bytes = SMEM_FLOATS * 4;
    static bool attr_done = false;
    if (!attr_done) {
        cudaFuncSetAttribute(k_transform, cudaFuncAttributeMaxDynamicSharedMemorySize,
                             smem_bytes);
        attr_done = true;
    }

    const int nb  = (n + 255) / 256;
    const int eb  = (e + 255) / 256;
    const int nbs = (n + 1023) / 1024;
    const int ab  = (n * 16 + 255) / 256;       // aggregate: half-warp per node
    const int ntiles = (n + 31) / 32;
    const int tb  = 592;                        // 4 blocks per SM

    // CSR build (grouped by destination)
    k_zero_deg<<<nb, 256>>>(n);
    k_count<<<eb, 256>>>(ei, e);
    k_blocksum<<<nbs, 256>>>(n);
    k_offsets<<<nbs, 256>>>(n, e);
    k_place<<<eb, 256>>>(ei, e);

    // layer 1: x -> hA
    k_aggregate<<<ab, 256>>>(x, n);
    k_transform<<<tb, 64, smem_bytes>>>(x, Wl1, bl1, Wr1, hA, n, ntiles);

    // layer 2: hA -> hB
    k_aggregate<<<ab, 256>>>(hA, n);
    k_transform<<<tb, 64, smem_bytes>>>(hA, Wl2, bl2, Wr2, hB, n, ntiles);

    // layer 3: hB -> hA
    k_aggregate<<<ab, 256>>>(hB, n);
    k_transform<<<tb, 64, smem_bytes>>>(hB, Wl3, bl3, Wr3, hA, n, ntiles);

    // head
    k_out<<<(n * 32 + 255) / 256, 256>>>(hA, Wo, bo, out, n);
}

// round 5
// speedup vs baseline: 1.9816x; 1.1334x over previous
#include <cuda_runtime.h>
#include <cuda_fp16.h>

#define NMAX 50000
#define EMAX 800000

// Scratch (device globals -- no allocation allowed in kernel_launch)
__device__ float  g_agg[NMAX * 64];
__device__ float  g_hA[NMAX * 64];
__device__ float  g_hB[NMAX * 64];
__device__ __half g_x16[NMAX * 64];
__device__ __half g_h16A[NMAX * 64];
__device__ __half g_h16B[NMAX * 64];
__device__ int    g_deg[NMAX];
__device__ int    g_off[NMAX + 1];
__device__ int    g_cur[NMAX];
__device__ int    g_csr[EMAX];
__device__ int    g_bsum[128];

// ---------------- fp32 -> fp16 conversion (+ fused deg zeroing) ----------------
// one thread converts 8 floats; first n threads also zero g_deg.

__global__ void k_tofp16_zero(const float* __restrict__ src, __half* __restrict__ dst,
                              int n8, int n) {
    int i = blockIdx.x * blockDim.x + threadIdx.x;
    if (i < n) g_deg[i] = 0;
    if (i >= n8) return;
    float4 a = ((const float4*)src)[i * 2];
    float4 b = ((const float4*)src)[i * 2 + 1];
    __half2 h0 = __floats2half2_rn(a.x, a.y);
    __half2 h1 = __floats2half2_rn(a.z, a.w);
    __half2 h2 = __floats2half2_rn(b.x, b.y);
    __half2 h3 = __floats2half2_rn(b.z, b.w);
    uint4 o;
    o.x = reinterpret_cast<unsigned&>(h0);
    o.y = reinterpret_cast<unsigned&>(h1);
    o.z = reinterpret_cast<unsigned&>(h2);
    o.w = reinterpret_cast<unsigned&>(h3);
    ((uint4*)dst)[i] = o;
}

// ---------------- CSR build ----------------

__global__ void k_count(const int* __restrict__ ei, int e) {
    int i = blockIdx.x * blockDim.x + threadIdx.x;
    if (i < e) atomicAdd(&g_deg[ei[e + i]], 1);   // row 1 of edge_index = dst
}

__global__ void k_blocksum(int n) {
    __shared__ int sm[256];
    int t = threadIdx.x, b = blockIdx.x;
    int base = b * 1024 + t * 4;
    int s = 0;
    #pragma unroll
    for (int u = 0; u < 4; u++) { int i = base + u; if (i < n) s += g_deg[i]; }
    sm[t] = s; __syncthreads();
    #pragma unroll
    for (int o = 128; o; o >>= 1) { if (t < o) sm[t] += sm[t + o]; __syncthreads(); }
    if (t == 0) g_bsum[b] = sm[0];
}

__global__ void k_offsets(int n, int e) {
    __shared__ int sm[256];
    int t = threadIdx.x, b = blockIdx.x;

    int v0 = (t < b) ? g_bsum[t] : 0;
    sm[t] = v0; __syncthreads();
    #pragma unroll
    for (int o = 128; o; o >>= 1) { if (t < o) sm[t] += sm[t + o]; __syncthreads(); }
    int bpre = sm[0];
    __syncthreads();

    int base = b * 1024 + t * 4;
    int vv[4]; int s = 0;
    #pragma unroll
    for (int u = 0; u < 4; u++) { vv[u] = (base + u < n) ? g_deg[base + u] : 0; s += vv[u]; }
    sm[t] = s; __syncthreads();
    #pragma unroll
    for (int o = 1; o < 256; o <<= 1) {
        int val = (t >= o) ? sm[t - o] : 0;
        __syncthreads();
        sm[t] += val;
        __syncthreads();
    }
    int excl = sm[t] - s + bpre;
    #pragma unroll
    for (int u = 0; u < 4; u++) {
        if (base + u < n) { g_off[base + u] = excl; g_cur[base + u] = excl; excl += vv[u]; }
    }
    if (b == 0 && t == 0) g_off[n] = e;
}

__global__ void k_place(const int* __restrict__ ei, int e) {
    int i = blockIdx.x * blockDim.x + threadIdx.x;
    if (i >= e) return;
    int s = ei[i];
    int d = ei[e + i];
    int pos = atomicAdd(&g_cur[d], 1);
    g_csr[pos] = s;
}

// ---------------- mean aggregation: 8 lanes/node, fp16 gather, fp32 accumulate ----------------
// each edge: 8 lanes x uint4 (8 halves) = 128 B = one L2 line.

__device__ __forceinline__ void addh(float2 acc[4], uint4 v) {
    float2 f;
    f = __half22float2(reinterpret_cast<__half2&>(v.x)); acc[0].x += f.x; acc[0].y += f.y;
    f = __half22float2(reinterpret_cast<__half2&>(v.y)); acc[1].x += f.x; acc[1].y += f.y;
    f = __half22float2(reinterpret_cast<__half2&>(v.z)); acc[2].x += f.x; acc[2].y += f.y;
    f = __half22float2(reinterpret_cast<__half2&>(v.w)); acc[3].x += f.x; acc[3].y += f.y;
}

__global__ void k_aggregate(const __half* __restrict__ h16, int n) {
    int t = blockIdx.x * blockDim.x + threadIdx.x;
    int node = t >> 3;
    int lane = t & 7;
    if (node >= n) return;
    int beg = g_off[node];
    int end = g_off[node + 1];

    float2 acc[4];
    acc[0] = acc[1] = acc[2] = acc[3] = make_float2(0.f, 0.f);

    int j = beg;
    for (; j + 3 < end; j += 4) {
        int s0 = __ldg(g_csr + j),     s1 = __ldg(g_csr + j + 1);
        int s2 = __ldg(g_csr + j + 2), s3 = __ldg(g_csr + j + 3);
        uint4 v0 = *(const uint4*)(h16 + (size_t)s0 * 64 + lane * 8);
        uint4 v1 = *(const uint4*)(h16 + (size_t)s1 * 64 + lane * 8);
        uint4 v2 = *(const uint4*)(h16 + (size_t)s2 * 64 + lane * 8);
        uint4 v3 = *(const uint4*)(h16 + (size_t)s3 * 64 + lane * 8);
        addh(acc, v0); addh(acc, v1); addh(acc, v2); addh(acc, v3);
    }
    for (; j < end; j++) {
        int s = __ldg(g_csr + j);
        uint4 v = *(const uint4*)(h16 + (size_t)s * 64 + lane * 8);
        addh(acc, v);
    }
    float inv = 1.0f / fmaxf((float)(end - beg), 1.0f);
    float4 o0 = make_float4(acc[0].x * inv, acc[0].y * inv, acc[1].x * inv, acc[1].y * inv);
    float4 o1 = make_float4(acc[2].x * inv, acc[2].y * inv, acc[3].x * inv, acc[3].y * inv);
    *(float4*)(g_agg + (size_t)node * 64 + lane * 8)     = o0;
    *(float4*)(g_agg + (size_t)node * 64 + lane * 8 + 4) = o1;
}

// ---------------- SAGE transform: persistent weights, grid-stride tiles ----------------
// out = leaky( [mean_nb | h] @ [Wl; Wr] + bl );  optionally fused output head.

__device__ __forceinline__ unsigned long long pack2(float a) {
    unsigned long long r;
    asm("mov.b64 %0, {%1, %1};" : "=l"(r) : "f"(a));
    return r;
}
__device__ __forceinline__ unsigned long long fma2(unsigned long long a,
                                                   unsigned long long b,
                                                   unsigned long long c) {
    unsigned long long d;
    asm("fma.rn.f32x2 %0, %1, %2, %3;" : "=l"(d) : "l"(a), "l"(b), "l"(c));
    return d;
}

#define ASTRIDE 132
#define SMEM_FLOATS (128 * 64 + 32 * ASTRIDE + 64)

__global__ void __launch_bounds__(64) k_transform(
    const float* __restrict__ h,
    const float* __restrict__ Wl, const float* __restrict__ bl,
    const float* __restrict__ Wr,
    float* __restrict__ out, __half* __restrict__ out16,
    const float* __restrict__ Wo, const float* __restrict__ bo,
    float* __restrict__ outv,
    int n, int ntiles, int do_head)
{
    extern __shared__ float smem[];
    float* Bs   = smem;                 // [128][64]: k<64 -> Wl, k>=64 -> Wr
    float* As   = smem + 128 * 64;      // [32][132]
    float* bias = As + 32 * ASTRIDE;    // [64]
    const int tid = threadIdx.x;

    {
        const float4* wl4 = (const float4*)Wl;
        const float4* wr4 = (const float4*)Wr;
        float4* bs4 = (float4*)Bs;
        #pragma unroll
        for (int i = 0; i < 16; i++) {
            bs4[i * 64 + tid]        = wl4[i * 64 + tid];
            bs4[1024 + i * 64 + tid] = wr4[i * 64 + tid];
        }
        if (tid < 16) ((float4*)bias)[tid] = ((const float4*)bl)[tid];
    }

    const int rg = tid >> 4;   // 0..3; rows rg + 4*i
    const int cg = tid & 15;   // cols cg*4..cg*4+3

    float4 wo = make_float4(0.f, 0.f, 0.f, 0.f);
    float bov = 0.f;
    if (do_head) { wo = *(const float4*)(Wo + cg * 4); bov = bo[0]; }

    for (int tile = blockIdx.x; tile < ntiles; tile += gridDim.x) {
        const int row0 = tile * 32;
        if (tile != blockIdx.x) __syncthreads();

        {
            #pragma unroll
            for (int ii = 0; ii < 16; ii++) {
                int i = ii * 64 + tid;
                int r = i >> 5;
                int q = i & 31;
                int gr = row0 + r;
                float4 v = make_float4(0.f, 0.f, 0.f, 0.f);
                if (gr < n) {
                    if (q < 16) v = *(const float4*)(g_agg + (size_t)gr * 64 + q * 4);
                    else        v = *(const float4*)(h + (size_t)gr * 64 + (q - 16) * 4);
                }
                *(float4*)(As + r * ASTRIDE + q * 4) = v;
            }
        }
        __syncthreads();

        unsigned long long acc0[8], acc1[8];
        #pragma unroll
        for (int i = 0; i < 8; i++) { acc0[i] = 0ull; acc1[i] = 0ull; }

        #pragma unroll 1
        for (int kc = 0; kc < 128; kc += 4) {
            float4 a4[8];
            #pragma unroll
            for (int i = 0; i < 8; i++)
                a4[i] = *(const float4*)(As + (rg + 4 * i) * ASTRIDE + kc);
            #pragma unroll
            for (int kk = 0; kk < 4; kk++) {
                ulonglong2 bb = *(const ulonglong2*)(Bs + (kc + kk) * 64 + cg * 4);
                #pragma unroll
                for (int i = 0; i < 8; i++) {
                    float av = ((const float*)&a4[i])[kk];
                    unsigned long long aa = pack2(av);
                    acc0[i] = fma2(aa, bb.x, acc0[i]);
                    acc1[i] = fma2(aa, bb.y, acc1[i]);
                }
            }
        }

        float4 bv = *(const float4*)(bias + cg * 4);
        #pragma unroll
        for (int i = 0; i < 8; i++) {
            int gr = row0 + rg + 4 * i;
            float4 o;
            asm("mov.b64 {%0, %1}, %2;" : "=f"(o.x), "=f"(o.y) : "l"(acc0[i]));
            asm("mov.b64 {%0, %1}, %2;" : "=f"(o.z), "=f"(o.w) : "l"(acc1[i]));
            o.x += bv.x; o.y += bv.y; o.z += bv.z; o.w += bv.w;
            o.x = o.x > 0.f ? o.x : 0.01f * o.x;
            o.y = o.y > 0.f ? o.y : 0.01f * o.y;
            o.z = o.z > 0.f ? o.z : 0.01f * o.z;
            o.w = o.w > 0.f ? o.w : 0.01f * o.w;
            if (do_head) {
                float p = o.x * wo.x + o.y * wo.y + o.z * wo.z + o.w * wo.w;
                p += __shfl_xor_sync(0xffffffffu, p, 1);
                p += __shfl_xor_sync(0xffffffffu, p, 2);
                p += __shfl_xor_sync(0xffffffffu, p, 4);
                p += __shfl_xor_sync(0xffffffffu, p, 8);
                if (cg == 0 && gr < n) outv[gr] = p + bov;
            } else if (gr < n) {
                *(float4*)(out + (size_t)gr * 64 + cg * 4) = o;
                __half2 p0 = __floats2half2_rn(o.x, o.y);
                __half2 p1 = __floats2half2_rn(o.z, o.w);
                uint2 u;
                u.x = reinterpret_cast<unsigned&>(p0);
                u.y = reinterpret_cast<unsigned&>(p1);
                *(uint2*)(out16 + (size_t)gr * 64 + cg * 4) = u;
            }
        }
    }
}

extern "C" void kernel_launch(void* const* d_in, const int* in_sizes, int n_in,
                              void* d_out, int out_size)
{
    const float* x   = (const float*)d_in[0];
    const int*   ei  = (const int*)d_in[1];
    const float* Wl1 = (const float*)d_in[2];
    const float* bl1 = (const float*)d_in[3];
    const float* Wr1 = (const float*)d_in[4];
    const float* Wl2 = (const float*)d_in[5];
    const float* bl2 = (const float*)d_in[6];
    const float* Wr2 = (const float*)d_in[7];
    const float* Wl3 = (const float*)d_in[8];
    const float* bl3 = (const float*)d_in[9];
    const float* Wr3 = (const float*)d_in[10];
    const float* Wo  = (const float*)d_in[11];
    const float* bo  = (const float*)d_in[12];
    float* out = (float*)d_out;

    const int n = in_sizes[0] / 64;
    const int e = in_sizes[1] / 2;

    float *hA = nullptr, *hB = nullptr;
    __half *x16 = nullptr, *h16A = nullptr, *h16B = nullptr;
    cudaGetSymbolAddress((void**)&hA, g_hA);
    cudaGetSymbolAddress((void**)&hB, g_hB);
    cudaGetSymbolAddress((void**)&x16, g_x16);
    cudaGetSymbolAddress((void**)&h16A, g_h16A);
    cudaGetSymbolAddress((void**)&h16B, g_h16B);

    const int smem_bytes = SMEM_FLOATS * 4;
    cudaFuncSetAttribute(k_transform, cudaFuncAttributeMaxDynamicSharedMemorySize,
                         smem_bytes);

    const int n8  = n * 8;                       // float4-pairs in x
    const int cb  = (n8 + 255) / 256;
    const int eb  = (e + 255) / 256;
    const int nbs = (n + 1023) / 1024;
    const int ab  = (n * 8 + 255) / 256;         // aggregate: 8 lanes per node
    const int ntiles = (n + 31) / 32;
    const int tb  = 592;

    // conversion + deg zeroing, then CSR build
    k_tofp16_zero<<<cb, 256>>>(x, x16, n8, n);
    k_count<<<eb, 256>>>(ei, e);
    k_blocksum<<<nbs, 256>>>(n);
    k_offsets<<<nbs, 256>>>(n, e);
    k_place<<<eb, 256>>>(ei, e);

    // layer 1: x -> hA (+h16A)
    k_aggregate<<<ab, 256>>>(x16, n);
    k_transform<<<tb, 64, smem_bytes>>>(x, Wl1, bl1, Wr1, hA, h16A,
                                        nullptr, nullptr, nullptr, n, ntiles, 0);
    // layer 2: hA -> hB (+h16B)
    k_aggregate<<<ab, 256>>>(h16A, n);
    k_transform<<<tb, 64, smem_bytes>>>(hA, Wl2, bl2, Wr2, hB, h16B,
                                        nullptr, nullptr, nullptr, n, ntiles, 0);
    // layer 3 + head: hB -> out
    k_aggregate<<<ab, 256>>>(h16B, n);
    k_transform<<<tb, 64, smem_bytes>>>(hB, Wl3, bl3, Wr3, nullptr, nullptr,
                                        Wo, bo, out, n, ntiles, 1);
}